// round 17
// baseline (speedup 1.0000x reference)
#include <cuda_runtime.h>
#include <cstdint>
#include <math.h>

// ----------------------------------------------------------------------------
// GraphSAGE (2-layer weighted-mean SAGEConv) on sm_100a.
// L1: agg1 = sum(w*X[src]); H = dropout(relu(l2norm((agg1/deg)@Wl1 + X@Wr1 + b1)))
// node1 (fused): P = H@Wl2, ZH = H@Wr2      (linearity: mean(w*H)@Wl2 == mean(w*P))
// L2: aggP = sum(w*P[src]); Z = aggP/deg + ZH + b2; out = log_softmax(Z)
// A is int32. Dropout = jax partitionable threefry, key(42): counter (0,i),
// word = y0^y1, keep <=> top bit == 0.
// Scatter-RED edges (CSR-gather variant measured SLOWER on this chip).
// edge2 uses the exact 10-threads/edge mapping (no idle lanes).
// ----------------------------------------------------------------------------

#define N_NODES 100000
#define N_EDGES 1600000
#define D_IN    32
#define D_HID   64
#define D_OUT   40
#define MASK_N  (N_NODES * D_HID)

// Scratch (device globals). float4-typed => 16B aligned.
__device__ float4        g_agg1[N_NODES * (D_IN / 4)];    // 12.8 MB
__device__ float4        g_deg4[N_NODES / 4];             // 0.4 MB
__device__ float4        g_P   [N_NODES * 10];            // 16 MB (40 f/node)
__device__ float4        g_ZH  [N_NODES * 10];            // 16 MB
__device__ float4        g_aggP[N_NODES * 10];            // 16 MB
__device__ unsigned char g_mask[MASK_N];                  // 6.4 MB

// ---------------------------------------------------------------------------
__device__ __forceinline__ void red_add_v4(float4* p, float4 v) {
    asm volatile(
        "{\n\t"
        ".reg .u64 gp;\n\t"
        "cvta.to.global.u64 gp, %0;\n\t"
        "red.global.add.v4.f32 [gp], {%1, %2, %3, %4};\n\t"
        "}"
        :: "l"(p), "f"(v.x), "f"(v.y), "f"(v.z), "f"(v.w)
        : "memory");
}

__device__ __forceinline__ uint32_t rotl32(uint32_t x, int r) {
    return __funnelshift_l(x, x, r);
}

// ---------------------------------------------------------------------------
// init: threefry mask (4 chains/thread) + zero accumulators, one launch.
// ---------------------------------------------------------------------------
__global__ __launch_bounds__(256) void init_kernel() {
    int t = blockIdx.x * blockDim.x + threadIdx.x;   // 1.6M threads
    uint32_t base = (uint32_t)t * 4u;

    if (base < (uint32_t)MASK_N) {
        const uint32_t ks0 = 0u;
        const uint32_t ks1 = 42u;
        const uint32_t ks2 = 0x1BD11BDAu ^ 0u ^ 42u;

        uint32_t a0 = ks0, a1 = ks0, a2 = ks0, a3 = ks0;
        uint32_t b0 = base + 0u + ks1, b1v = base + 1u + ks1;
        uint32_t b2v = base + 2u + ks1, b3 = base + 3u + ks1;

#define TF4(r) { \
    a0 += b0;  b0  = rotl32(b0,  (r)); b0  ^= a0; \
    a1 += b1v; b1v = rotl32(b1v, (r)); b1v ^= a1; \
    a2 += b2v; b2v = rotl32(b2v, (r)); b2v ^= a2; \
    a3 += b3;  b3  = rotl32(b3,  (r)); b3  ^= a3; }
#define INJ4(ka, kb, c) { \
    a0 += (ka); b0  += (kb) + (c); a1 += (ka); b1v += (kb) + (c); \
    a2 += (ka); b2v += (kb) + (c); a3 += (ka); b3  += (kb) + (c); }

        TF4(13) TF4(15) TF4(26) TF4(6)
        INJ4(ks1, ks2, 1u)
        TF4(17) TF4(29) TF4(16) TF4(24)
        INJ4(ks2, ks0, 2u)
        TF4(13) TF4(15) TF4(26) TF4(6)
        INJ4(ks0, ks1, 3u)
        TF4(17) TF4(29) TF4(16) TF4(24)
        INJ4(ks1, ks2, 4u)
        TF4(13) TF4(15) TF4(26) TF4(6)
        INJ4(ks2, ks0, 5u)
#undef TF4
#undef INJ4

        uchar4 m;
        m.x = (unsigned char)((((a0 ^ b0)  >> 31) ^ 1u) & 1u);
        m.y = (unsigned char)((((a1 ^ b1v) >> 31) ^ 1u) & 1u);
        m.z = (unsigned char)((((a2 ^ b2v) >> 31) ^ 1u) & 1u);
        m.w = (unsigned char)((((a3 ^ b3)  >> 31) ^ 1u) & 1u);
        ((uchar4*)g_mask)[t] = m;
    }

    // zeroing (grid-stride; 1.6M threads)
    int stride = gridDim.x * blockDim.x;
    float4 z = make_float4(0.f, 0.f, 0.f, 0.f);
    for (int j = t; j < 800000;  j += stride) g_agg1[j] = z;
    for (int j = t; j < 1000000; j += stride) g_aggP[j] = z;
    for (int j = t; j < 25000;   j += stride) g_deg4[j] = z;
}

// ---------------------------------------------------------------------------
// layer-1 edge scatter: agg1[dst] += X[src]*w (8 x float4), deg[dst] += 1.
// ---------------------------------------------------------------------------
__global__ __launch_bounds__(256) void edge1_kernel(const float* __restrict__ X,
                                                    const int* __restrict__ A,
                                                    const float* __restrict__ W) {
    int t = blockIdx.x * blockDim.x + threadIdx.x;
    int e = t >> 3;
    int c = t & 7;
    if (e >= N_EDGES) return;
    int lane = threadIdx.x & 31;
    int srcLane = lane & ~7;

    int s = 0, d = 0; float w = 0.f;
    if (c == 0) {
        s = A[e];
        d = A[N_EDGES + e];
        w = W[e];
    }
    s = __shfl_sync(0xffffffffu, s, srcLane);
    d = __shfl_sync(0xffffffffu, d, srcLane);
    w = __shfl_sync(0xffffffffu, w, srcLane);

    float4 xv = ((const float4*)X)[s * 8 + c];
    float4 m = make_float4(xv.x * w, xv.y * w, xv.z * w, xv.w * w);
    red_add_v4(&g_agg1[d * 8 + c], m);
    if (c == 0) atomicAdd((float*)g_deg4 + d, 1.0f);
}

// ---------------------------------------------------------------------------
// Fused node kernel: 4 nodes/warp, 32 nodes/block, grid 3125.
//  Phase A: H = dropout(relu(l2norm((agg1/deg)@Wl1 + X@Wr1 + b1)))
//  Phase B: P = H@Wl2 -> g_P ; ZH = H@Wr2 -> g_ZH
// One 32KB weight buffer, reloaded between phases (L2-resident reads).
// ---------------------------------------------------------------------------
__global__ __launch_bounds__(256) void node1_kernel(
        const float* __restrict__ X,
        const float* __restrict__ Wl1,
        const float* __restrict__ Wr1,
        const float* __restrict__ b1,
        const float* __restrict__ Wl2,
        const float* __restrict__ Wr2) {
    __shared__ float4 sW[2048];                 // 32 KB, overlaid A/B weights
    __shared__ float  sBuf[32][D_HID];          // inputs then H, 8 KB

    int tid  = threadIdx.x;
    int warp = tid >> 5, lane = tid & 31;

    // Phase-A weights: sW[k*32+j] = (wl_j, wl_j32, wr_j, wr_j32), k<32
    for (int i = tid; i < D_IN * 32; i += 256) {
        int k = i >> 5, j = i & 31;
        sW[i] = make_float4(Wl1[k * D_HID + j], Wl1[k * D_HID + j + 32],
                            Wr1[k * D_HID + j], Wr1[k * D_HID + j + 32]);
    }

    int nodeBase = blockIdx.x * 32 + warp * 4;       // grid 3125 -> exact
    const float* agg1 = (const float*)g_agg1;
    const float* deg  = (const float*)g_deg4;

    // stage inputs: sBuf[row][2k]=a_k, [2k+1]=x_k  (k = lane)
#pragma unroll
    for (int nn = 0; nn < 4; nn++) {
        int node = nodeBase + nn;
        float inv = 1.0f / fmaxf(deg[node], 1.0f);
        float a = agg1[node * D_IN + lane] * inv;
        float x = X[node * D_IN + lane];
        *(float2*)&sBuf[warp * 4 + nn][2 * lane] = make_float2(a, x);
    }
    __syncthreads();

    // ---- Phase A ----
    float acc0[4], acc1[4];
    {
        float bb0 = b1[lane], bb1 = b1[lane + 32];
#pragma unroll
        for (int nn = 0; nn < 4; nn++) { acc0[nn] = bb0; acc1[nn] = bb1; }
    }
#pragma unroll
    for (int k2 = 0; k2 < D_IN / 2; k2++) {
        float4 wa = sW[(2 * k2) * 32 + lane];
        float4 wb = sW[(2 * k2 + 1) * 32 + lane];
#pragma unroll
        for (int nn = 0; nn < 4; nn++) {
            float4 ax = *(const float4*)&sBuf[warp * 4 + nn][4 * k2]; // a0,x0,a1,x1
            acc0[nn] += ax.x * wa.x + ax.y * wa.z + ax.z * wb.x + ax.w * wb.z;
            acc1[nn] += ax.x * wa.y + ax.y * wa.w + ax.z * wb.y + ax.w * wb.w;
        }
    }
    __syncthreads();   // everyone done reading phase-A weights

    // Reload sW with phase-B weights (Wl2 in [0..1023], Wr2 in [1024..2047])
    for (int i = tid; i < (D_HID / 2) * 32; i += 256) {
        int k2 = i >> 5, j = i & 31;
        bool hi = (j + 32 < D_OUT);
        sW[i]        = make_float4(Wl2[(2 * k2) * D_OUT + j],
                                   hi ? Wl2[(2 * k2) * D_OUT + j + 32] : 0.f,
                                   Wl2[(2 * k2 + 1) * D_OUT + j],
                                   hi ? Wl2[(2 * k2 + 1) * D_OUT + j + 32] : 0.f);
        sW[1024 + i] = make_float4(Wr2[(2 * k2) * D_OUT + j],
                                   hi ? Wr2[(2 * k2) * D_OUT + j + 32] : 0.f,
                                   Wr2[(2 * k2 + 1) * D_OUT + j],
                                   hi ? Wr2[(2 * k2 + 1) * D_OUT + j + 32] : 0.f);
    }

    // norm + relu + dropout; H overwrites sBuf rows (warp-private rows)
#pragma unroll
    for (int nn = 0; nn < 4; nn++) {
        float ss = acc0[nn] * acc0[nn] + acc1[nn] * acc1[nn];
#pragma unroll
        for (int o = 16; o > 0; o >>= 1) ss += __shfl_xor_sync(0xffffffffu, ss, o);
        float scale = rsqrtf(fmaxf(ss, 1e-24f));

        float h0 = fmaxf(acc0[nn] * scale, 0.0f);
        float h1 = fmaxf(acc1[nn] * scale, 0.0f);
        int mbase = (nodeBase + nn) * D_HID;
        h0 = g_mask[mbase + lane]      ? 2.0f * h0 : 0.0f;
        h1 = g_mask[mbase + lane + 32] ? 2.0f * h1 : 0.0f;
        sBuf[warp * 4 + nn][lane]      = h0;
        sBuf[warp * 4 + nn][lane + 32] = h1;
    }
    __syncthreads();   // weights loaded + H in place

    // ---- Phase B: P = H@Wl2, ZH = H@Wr2 ----
    float p0[4] = {0.f, 0.f, 0.f, 0.f}, p1[4] = {0.f, 0.f, 0.f, 0.f};
    float q0[4] = {0.f, 0.f, 0.f, 0.f}, q1[4] = {0.f, 0.f, 0.f, 0.f};
#pragma unroll
    for (int m = 0; m < D_HID / 4; m++) {        // 4 k per iter
        float4 w2a = sW[(2 * m) * 32 + lane];
        float4 w2b = sW[(2 * m + 1) * 32 + lane];
        float4 wra = sW[1024 + (2 * m) * 32 + lane];
        float4 wrb = sW[1024 + (2 * m + 1) * 32 + lane];
#pragma unroll
        for (int nn = 0; nn < 4; nn++) {
            float4 h = *(const float4*)&sBuf[warp * 4 + nn][4 * m];
            p0[nn] += h.x * w2a.x + h.y * w2a.z + h.z * w2b.x + h.w * w2b.z;
            p1[nn] += h.x * w2a.y + h.y * w2a.w + h.z * w2b.y + h.w * w2b.w;
            q0[nn] += h.x * wra.x + h.y * wra.z + h.z * wrb.x + h.w * wrb.z;
            q1[nn] += h.x * wra.y + h.y * wra.w + h.z * wrb.y + h.w * wrb.w;
        }
    }

    float* P  = (float*)g_P;
    float* ZH = (float*)g_ZH;
#pragma unroll
    for (int nn = 0; nn < 4; nn++) {
        int base = (nodeBase + nn) * D_OUT;
        P[base + lane]  = p0[nn];
        ZH[base + lane] = q0[nn];
        if (lane < 8) {
            P[base + 32 + lane]  = p1[nn];
            ZH[base + 32 + lane] = q1[nn];
        }
    }
}

// ---------------------------------------------------------------------------
// layer-2 edge scatter on P: aggP[dst] += P[src]*w. Exact 10 threads/edge,
// no idle lanes; per-thread index loads hit the same L1 lines across an edge.
// ---------------------------------------------------------------------------
__global__ __launch_bounds__(256) void edge2_kernel(const int* __restrict__ A,
                                                    const float* __restrict__ W) {
    int t = blockIdx.x * blockDim.x + threadIdx.x;   // 16M threads exact
    int e = t / 10;
    int c = t - e * 10;
    if (e >= N_EDGES) return;

    int   s = A[e];
    int   d = A[N_EDGES + e];
    float w = W[e];

    float4 pv = g_P[s * 10 + c];
    float4 m = make_float4(pv.x * w, pv.y * w, pv.z * w, pv.w * w);
    red_add_v4(&g_aggP[d * 10 + c], m);
}

// ---------------------------------------------------------------------------
// layer-2 finish: Z = aggP/deg + ZH + b2; out = log_softmax(Z).
// Pure elementwise + warp softmax. 4 nodes/warp.
// ---------------------------------------------------------------------------
__global__ __launch_bounds__(256) void node2_kernel(const float* __restrict__ b2,
                                                    float* __restrict__ out) {
    int tid  = threadIdx.x;
    int warp = tid >> 5, lane = tid & 31;
    int nodeBase = blockIdx.x * 32 + warp * 4;

    const float* aggP = (const float*)g_aggP;
    const float* ZH   = (const float*)g_ZH;
    const float* deg  = (const float*)g_deg4;
    float bb0 = b2[lane];
    float bb1 = (lane < 8) ? b2[lane + 32] : 0.0f;

#pragma unroll
    for (int nn = 0; nn < 4; nn++) {
        int node = nodeBase + nn;
        float inv = 1.0f / fmaxf(deg[node], 1.0f);
        int base = node * D_OUT;

        float v0 = aggP[base + lane] * inv + ZH[base + lane] + bb0;
        float v1 = (lane < 8)
                 ? aggP[base + 32 + lane] * inv + ZH[base + 32 + lane] + bb1
                 : 0.0f;

        float m = (lane < 8) ? fmaxf(v0, v1) : v0;
#pragma unroll
        for (int o = 16; o > 0; o >>= 1) m = fmaxf(m, __shfl_xor_sync(0xffffffffu, m, o));
        float ssum = expf(v0 - m) + ((lane < 8) ? expf(v1 - m) : 0.0f);
#pragma unroll
        for (int o = 16; o > 0; o >>= 1) ssum += __shfl_xor_sync(0xffffffffu, ssum, o);
        float lse = m + logf(ssum);

        out[base + lane] = v0 - lse;
        if (lane < 8) out[base + 32 + lane] = v1 - lse;
    }
}

// ---------------------------------------------------------------------------
extern "C" void kernel_launch(void* const* d_in, const int* in_sizes, int n_in,
                              void* d_out, int out_size) {
    const float* X   = (const float*)d_in[0];
    const int*   A   = (const int*)d_in[1];     // int32 (JAX x64 disabled)
    const float* W   = (const float*)d_in[2];
    const float* Wl1 = (const float*)d_in[3];
    const float* Wr1 = (const float*)d_in[4];
    const float* b1  = (const float*)d_in[5];
    const float* Wl2 = (const float*)d_in[6];
    const float* Wr2 = (const float*)d_in[7];
    const float* b2  = (const float*)d_in[8];
    float*       out = (float*)d_out;

    init_kernel<<<MASK_N / (256 * 4), 256>>>();
    edge1_kernel<<<(N_EDGES * 8) / 256, 256>>>(X, A, W);
    node1_kernel<<<N_NODES / 32, 256>>>(X, Wl1, Wr1, b1, Wl2, Wr2);
    edge2_kernel<<<(N_EDGES * 10) / 256, 256>>>(A, W);
    node2_kernel<<<N_NODES / 32, 256>>>(b2, out);
}